// round 1
// baseline (speedup 1.0000x reference)
#include <cuda_runtime.h>

#define NP 100000
#define KN 16
#define NK (NP*KN)

// ---------------- device scratch (no allocation allowed) ----------------
__device__ int   g_cnt[NP];            // occurrence counts of each point in knn
__device__ float g_g1[NP*64];          // f-path layer1 pre-BN (per unique point)
__device__ float g_g2[NP*64];          // f-path layer2 pre-BN
__device__ float g_y1w[NK*8];          // w-path layer1 pre-BN  [ (n*K+k)*8 + o ]
__device__ float g_y2w[NK*8];          // w-path layer2 pre-BN
__device__ float g_new[NP*1024];       // new_flat (N, H*MID)
__device__ float g_z[NP*64];           // pre-final-BN output
__device__ float g_stats[448];         // sums / sumsq, segmented
__device__ float g_ss[448];            // finalized scale / shift, same layout

// stats segment offsets: [off, off+nch) = sum, [off+nch, off+2nch) = sumsq
#define F1_OFF 0     // 64 ch
#define W1_OFF 128   // 8 ch
#define F2_OFF 144   // 64 ch
#define W2_OFF 272   // 8 ch
#define W3_OFF 288   // 16 ch
#define Z_OFF  320   // 64 ch

#define EPS_BN 1e-5f

// ---------------- init ----------------
__global__ void k_zero() {
    int i = blockIdx.x * 256 + threadIdx.x;
    if (i < NP)  g_cnt[i] = 0;
    if (i < 448) g_stats[i] = 0.f;
}

__global__ void k_cnt(const int* __restrict__ knn) {
    int i = blockIdx.x * 256 + threadIdx.x;
    if (i < NK) atomicAdd(&g_cnt[knn[i]], 1);
}

// ---------------- stats helper: warp -> block -> one atomic per channel ----------------
template<int CH>
__device__ __forceinline__ void stats_reduce(float* ls, float* lss, int off) {
    const unsigned FULL = 0xffffffffu;
    #pragma unroll
    for (int c = 0; c < CH; c++) {
        #pragma unroll
        for (int o = 16; o; o >>= 1) {
            ls[c]  += __shfl_down_sync(FULL, ls[c],  o);
            lss[c] += __shfl_down_sync(FULL, lss[c], o);
        }
    }
    __shared__ float sred[2 * 8 * CH];   // 8 warps (blockDim = 256)
    int wid = threadIdx.x >> 5, lane = threadIdx.x & 31;
    if (lane == 0) {
        #pragma unroll
        for (int c = 0; c < CH; c++) {
            sred[wid * CH + c]            = ls[c];
            sred[8 * CH + wid * CH + c]   = lss[c];
        }
    }
    __syncthreads();
    if (threadIdx.x < CH) {
        float a = 0.f, b = 0.f;
        #pragma unroll
        for (int w = 0; w < 8; w++) {
            a += sred[w * CH + threadIdx.x];
            b += sred[8 * CH + w * CH + threadIdx.x];
        }
        atomicAdd(&g_stats[off + threadIdx.x], a);
        atomicAdd(&g_stats[off + CH + threadIdx.x], b);
    }
}

// ---------------- f-path conv (64 -> 64), per UNIQUE point, count-weighted stats ----------------
// STAGE 0: input = feats, output = g_g1, stats F1
// STAGE 1: input = relu(BN_F1(g_g1)), output = g_g2, stats F2
template<int STAGE>
__global__ __launch_bounds__(256) void k_fconv(const float* __restrict__ in,
                                               const float* __restrict__ W,
                                               const float* __restrict__ B) {
    __shared__ float wsm[64 * 64];   // transposed: wsm[c*64 + h]
    __shared__ float xsm[4 * 64];
    __shared__ float red[256];
    int t = threadIdx.x, ch = t & 63, sub = t >> 6;
    for (int i = t; i < 4096; i += 256) {
        int h = i >> 6, c = i & 63;
        wsm[c * 64 + h] = W[i];
    }
    float sc = 0.f, sh = 0.f;
    if (STAGE == 1) { sc = g_ss[F1_OFF + ch]; sh = g_ss[F1_OFF + 64 + ch]; }
    float bias = B[ch];
    float ls = 0.f, lss = 0.f;
    const float* src = (STAGE == 0) ? in : g_g1;
    float* dst = (STAGE == 0) ? g_g1 : g_g2;
    int ngrp = (NP + 3) >> 2;
    for (int grp = blockIdx.x; grp < ngrp; grp += gridDim.x) {
        int p = grp * 4 + sub;
        __syncthreads();
        float xv = 0.f;
        if (p < NP) {
            xv = src[p * 64 + ch];
            if (STAGE == 1) xv = fmaxf(sc * xv + sh, 0.f);
        }
        xsm[t] = xv;
        __syncthreads();
        if (p < NP) {
            const float* x = &xsm[sub * 64];
            float acc = bias;
            #pragma unroll
            for (int c = 0; c < 64; c++) acc += wsm[c * 64 + ch] * x[c];
            dst[p * 64 + ch] = acc;
            float w = (float)g_cnt[p];
            ls += w * acc;
            lss += w * acc * acc;
        }
    }
    __syncthreads();
    red[t] = ls; __syncthreads();
    if (t < 64) {
        float v = red[t] + red[t + 64] + red[t + 128] + red[t + 192];
        atomicAdd(&g_stats[(STAGE == 0 ? F1_OFF : F2_OFF) + t], v);
    }
    __syncthreads();
    red[t] = lss; __syncthreads();
    if (t < 64) {
        float v = red[t] + red[t + 64] + red[t + 128] + red[t + 192];
        atomicAdd(&g_stats[(STAGE == 0 ? F1_OFF : F2_OFF) + 64 + t], v);
    }
}

// ---------------- w-path layer 1: geometry features -> 14 -> 8 ----------------
__global__ __launch_bounds__(256) void k_w1(const float* __restrict__ xyz,
                                            const float* __restrict__ cov,
                                            const float* __restrict__ feats,
                                            const int* __restrict__ knn,
                                            const float* __restrict__ ww1,
                                            const float* __restrict__ wb1) {
    __shared__ float wsm[112];
    __shared__ float bsm[8];
    int t = threadIdx.x;
    if (t < 112) wsm[t] = ww1[t];
    if (t < 8)   bsm[t] = wb1[t];
    __syncthreads();
    float ls[8], lss[8];
    #pragma unroll
    for (int o = 0; o < 8; o++) { ls[o] = 0.f; lss[o] = 0.f; }
    for (int i = blockIdx.x * 256 + t; i < NK; i += gridDim.x * 256) {
        int n = i >> 4;
        int j  = knn[i];
        int j0 = knn[n << 4];
        float lx = xyz[j * 3 + 0] - xyz[j0 * 3 + 0];
        float ly = xyz[j * 3 + 1] - xyz[j0 * 3 + 1];
        float lz = xyz[j * 3 + 2] - xyz[j0 * 3 + 2];
        float nax = feats[j * 64 + 3],  nay = feats[j * 64 + 4],  naz = feats[j * 64 + 5];
        float nmx = feats[j0 * 64 + 3], nmy = feats[j0 * 64 + 4], nmz = feats[j0 * 64 + 5];
        float rn = sqrtf(lx * lx + ly * ly + lz * lz);
        float inv = 1.f / fmaxf(rn, 1e-12f);
        float rx = lx * inv, ry = ly * inv, rz = lz * inv;
        float dot = nmx * rx + nmy * ry + nmz * rz;
        float vx = nmx - dot * rx, vy = nmy - dot * ry, vz = nmz - dot * rz;
        float vi = 1.f / fmaxf(sqrtf(vx * vx + vy * vy + vz * vz), 1e-12f);
        vx *= vi; vy *= vi; vz *= vi;
        float wx = ry * vz - rz * vy;
        float wy = rz * vx - rx * vz;
        float wz = rx * vy - ry * vx;
        float wi = 1.f / fmaxf(sqrtf(wx * wx + wy * wy + wz * wz), 1e-12f);
        wx *= wi; wy *= wi; wz *= wi;
        float t1 = nax * nmx + nay * nmy + naz * nmz;
        float t3 = rx * nax + ry * nay + rz * naz;
        float t4 = lx * nmx + ly * nmy + lz * nmz;
        float t6 = nax * vx + nay * vy + naz * vz;
        float t7 = nax * wx + nay * wy + naz * wz;
        float cx = nay * nmz - naz * nmy;
        float cy = naz * nmx - nax * nmz;
        float cz = nax * nmy - nay * nmx;
        float t8 = lx * cx + ly * cy + lz * cz;
        const float* cg = &cov[j * 9];
        float s1 = lx * (cg[0] * lx + cg[1] * ly + cg[2] * lz)
                 + ly * (cg[3] * lx + cg[4] * ly + cg[5] * lz)
                 + lz * (cg[6] * lx + cg[7] * ly + cg[8] * lz);
        const float* c0 = &cov[j0 * 9];
        float s2 = lx * (c0[0] * lx + c0[1] * ly + c0[2] * lz)
                 + ly * (c0[3] * lx + c0[4] * ly + c0[5] * lz)
                 + lz * (c0[6] * lx + c0[7] * ly + c0[8] * lz);
        float win[14] = {lx, ly, lz, t1, dot, t3, t4, t3, t6, t7, t8, rn, s1, s2};
        #pragma unroll
        for (int o = 0; o < 8; o++) {
            float y = bsm[o];
            #pragma unroll
            for (int c = 0; c < 14; c++) y += wsm[o * 14 + c] * win[c];
            g_y1w[i * 8 + o] = y;
            ls[o] += y; lss[o] += y * y;
        }
    }
    stats_reduce<8>(ls, lss, W1_OFF);
}

// ---------------- w-path layer 2: 8 -> 8 ----------------
__global__ __launch_bounds__(256) void k_w2(const float* __restrict__ ww2,
                                            const float* __restrict__ wb2) {
    __shared__ float wsm[64], bsm[8], ssc[8], ssh[8];
    int t = threadIdx.x;
    if (t < 64) wsm[t] = ww2[t];
    if (t < 8) { bsm[t] = wb2[t]; ssc[t] = g_ss[W1_OFF + t]; ssh[t] = g_ss[W1_OFF + 8 + t]; }
    __syncthreads();
    float ls[8], lss[8];
    #pragma unroll
    for (int o = 0; o < 8; o++) { ls[o] = 0.f; lss[o] = 0.f; }
    for (int i = blockIdx.x * 256 + t; i < NK; i += gridDim.x * 256) {
        float a[8];
        float4 a0 = *(const float4*)&g_y1w[i * 8];
        float4 a1 = *(const float4*)&g_y1w[i * 8 + 4];
        a[0] = a0.x; a[1] = a0.y; a[2] = a0.z; a[3] = a0.w;
        a[4] = a1.x; a[5] = a1.y; a[6] = a1.z; a[7] = a1.w;
        #pragma unroll
        for (int c = 0; c < 8; c++) a[c] = fmaxf(ssc[c] * a[c] + ssh[c], 0.f);
        #pragma unroll
        for (int o = 0; o < 8; o++) {
            float y = bsm[o];
            #pragma unroll
            for (int c = 0; c < 8; c++) y += wsm[o * 8 + c] * a[c];
            g_y2w[i * 8 + o] = y;
            ls[o] += y; lss[o] += y * y;
        }
    }
    stats_reduce<8>(ls, lss, W2_OFF);
}

// ---------------- w-path layer 3: stats only (y3 recomputed in k_new) ----------------
__global__ __launch_bounds__(256) void k_w3s(const float* __restrict__ ww3,
                                             const float* __restrict__ wb3) {
    __shared__ float wsm[128], bsm[16], ssc[8], ssh[8];
    int t = threadIdx.x;
    if (t < 128) wsm[t] = ww3[t];
    if (t < 16)  bsm[t] = wb3[t];
    if (t < 8) { ssc[t] = g_ss[W2_OFF + t]; ssh[t] = g_ss[W2_OFF + 8 + t]; }
    __syncthreads();
    float ls[16], lss[16];
    #pragma unroll
    for (int o = 0; o < 16; o++) { ls[o] = 0.f; lss[o] = 0.f; }
    for (int i = blockIdx.x * 256 + t; i < NK; i += gridDim.x * 256) {
        float a[8];
        float4 a0 = *(const float4*)&g_y2w[i * 8];
        float4 a1 = *(const float4*)&g_y2w[i * 8 + 4];
        a[0] = a0.x; a[1] = a0.y; a[2] = a0.z; a[3] = a0.w;
        a[4] = a1.x; a[5] = a1.y; a[6] = a1.z; a[7] = a1.w;
        #pragma unroll
        for (int c = 0; c < 8; c++) a[c] = fmaxf(ssc[c] * a[c] + ssh[c], 0.f);
        #pragma unroll
        for (int o = 0; o < 16; o++) {
            float y = bsm[o];
            #pragma unroll
            for (int c = 0; c < 8; c++) y += wsm[o * 8 + c] * a[c];
            ls[o] += y; lss[o] += y * y;
        }
    }
    stats_reduce<16>(ls, lss, W3_OFF);
}

// ---------------- finalize BN: mean/var -> scale/shift ----------------
__global__ void k_fin(int off, const float* __restrict__ gamma,
                      const float* __restrict__ beta, int nch, float invc) {
    int c = threadIdx.x;
    if (c < nch) {
        float m = g_stats[off + c] * invc;
        float v = g_stats[off + nch + c] * invc - m * m;
        float s = gamma[c] / sqrtf(v + EPS_BN);
        g_ss[off + c] = s;
        g_ss[off + nch + c] = beta[c] - m * s;
    }
}

// ---------------- new = f @ w^T per point (64x16), store new_flat ----------------
__global__ __launch_bounds__(128) void k_new(const int* __restrict__ knn,
                                             const float* __restrict__ ww3,
                                             const float* __restrict__ wb3) {
    __shared__ float sw[256];          // w[m*16 + k], post-BN3-relu
    __shared__ int   sj[16];
    __shared__ float sww3[128], swb3[16], sc3[16], sh3[16], sc2[8], sh2[8];
    int t = threadIdx.x, n = blockIdx.x;
    if (t < 128) sww3[t] = ww3[t];
    if (t < 16) {
        swb3[t] = wb3[t];
        sc3[t] = g_ss[W3_OFF + t];
        sh3[t] = g_ss[W3_OFF + 16 + t];
        sj[t] = knn[n * 16 + t];
    }
    if (t >= 16 && t < 24) {
        int c = t - 16;
        sc2[c] = g_ss[W2_OFF + c];
        sh2[c] = g_ss[W2_OFF + 8 + c];
    }
    __syncthreads();
    if (t < 16) {
        int k = t;
        int base = (n * 16 + k) * 8;
        float a[8];
        float4 a0 = *(const float4*)&g_y2w[base];
        float4 a1 = *(const float4*)&g_y2w[base + 4];
        a[0] = a0.x; a[1] = a0.y; a[2] = a0.z; a[3] = a0.w;
        a[4] = a1.x; a[5] = a1.y; a[6] = a1.z; a[7] = a1.w;
        #pragma unroll
        for (int c = 0; c < 8; c++) a[c] = fmaxf(sc2[c] * a[c] + sh2[c], 0.f);
        #pragma unroll
        for (int m = 0; m < 16; m++) {
            float y = swb3[m];
            #pragma unroll
            for (int c = 0; c < 8; c++) y += sww3[m * 8 + c] * a[c];
            sw[m * 16 + k] = fmaxf(sc3[m] * y + sh3[m], 0.f);
        }
    }
    __syncthreads();
    int h = t >> 1, mb = (t & 1) * 8;
    float sc = g_ss[F2_OFF + h], sh = g_ss[F2_OFF + 64 + h];
    float fv[16];
    #pragma unroll
    for (int k = 0; k < 16; k++)
        fv[k] = fmaxf(sc * g_g2[sj[k] * 64 + h] + sh, 0.f);
    float out[8];
    #pragma unroll
    for (int mm = 0; mm < 8; mm++) {
        int m = mb + mm;
        float acc = 0.f;
        #pragma unroll
        for (int k = 0; k < 16; k++) acc += fv[k] * sw[m * 16 + k];
        out[mm] = acc;
    }
    float4* dst = (float4*)&g_new[n * 1024 + h * 16 + mb];
    dst[0] = make_float4(out[0], out[1], out[2], out[3]);
    dst[1] = make_float4(out[4], out[5], out[6], out[7]);
}

// ---------------- final GEMM: z = new_flat(100000x1024) @ lin_w^T(1024x64) + stats ----------------
__global__ __launch_bounds__(256) void k_lin(const float* __restrict__ lw,
                                             const float* __restrict__ lb) {
    __shared__ float A[128][16];
    __shared__ float Bs[16][64];
    __shared__ float sred[16][64];
    int t = threadIdx.x, tx = t & 15, ty = t >> 4;
    int rbase = blockIdx.x * 128;
    float acc[8][4];
    #pragma unroll
    for (int i = 0; i < 8; i++)
        #pragma unroll
        for (int j = 0; j < 4; j++) acc[i][j] = 0.f;

    for (int k0 = 0; k0 < 1024; k0 += 16) {
        __syncthreads();
        #pragma unroll
        for (int q = 0; q < 2; q++) {
            int id = t * 2 + q;
            int r = id >> 2, seg = id & 3;
            float4 v = make_float4(0.f, 0.f, 0.f, 0.f);
            if (rbase + r < NP) v = *(const float4*)&g_new[(rbase + r) * 1024 + k0 + seg * 4];
            *(float4*)&A[r][seg * 4] = v;
        }
        {
            int o = t >> 2, seg = t & 3;
            float4 v = *(const float4*)&lw[o * 1024 + k0 + seg * 4];
            Bs[seg * 4 + 0][o] = v.x;
            Bs[seg * 4 + 1][o] = v.y;
            Bs[seg * 4 + 2][o] = v.z;
            Bs[seg * 4 + 3][o] = v.w;
        }
        __syncthreads();
        #pragma unroll
        for (int kk = 0; kk < 16; kk++) {
            float a[8], b[4];
            #pragma unroll
            for (int i = 0; i < 8; i++) a[i] = A[ty * 8 + i][kk];
            #pragma unroll
            for (int j = 0; j < 4; j++) b[j] = Bs[kk][tx * 4 + j];
            #pragma unroll
            for (int i = 0; i < 8; i++)
                #pragma unroll
                for (int j = 0; j < 4; j++) acc[i][j] += a[i] * b[j];
        }
    }
    float s[4] = {0.f, 0.f, 0.f, 0.f}, ss[4] = {0.f, 0.f, 0.f, 0.f};
    #pragma unroll
    for (int j = 0; j < 4; j++) {
        float bb = lb[tx * 4 + j];
        #pragma unroll
        for (int i = 0; i < 8; i++) {
            int r = rbase + ty * 8 + i;
            if (r < NP) {
                float z = acc[i][j] + bb;
                g_z[r * 64 + tx * 4 + j] = z;
                s[j] += z; ss[j] += z * z;
            }
        }
    }
    // block reduce over ty, one atomic per column per block
    __syncthreads();
    #pragma unroll
    for (int j = 0; j < 4; j++) sred[ty][tx * 4 + j] = s[j];
    __syncthreads();
    #pragma unroll
    for (int off = 8; off; off >>= 1) {
        if (ty < off)
            #pragma unroll
            for (int j = 0; j < 4; j++) sred[ty][tx * 4 + j] += sred[ty + off][tx * 4 + j];
        __syncthreads();
    }
    if (ty == 0)
        #pragma unroll
        for (int j = 0; j < 4; j++) atomicAdd(&g_stats[Z_OFF + tx * 4 + j], sred[0][tx * 4 + j]);
    __syncthreads();
    #pragma unroll
    for (int j = 0; j < 4; j++) sred[ty][tx * 4 + j] = ss[j];
    __syncthreads();
    #pragma unroll
    for (int off = 8; off; off >>= 1) {
        if (ty < off)
            #pragma unroll
            for (int j = 0; j < 4; j++) sred[ty][tx * 4 + j] += sred[ty + off][tx * 4 + j];
        __syncthreads();
    }
    if (ty == 0)
        #pragma unroll
        for (int j = 0; j < 4; j++) atomicAdd(&g_stats[Z_OFF + 64 + tx * 4 + j], sred[0][tx * 4 + j]);
}

// ---------------- final BN + relu -> output ----------------
__global__ void k_out(float* __restrict__ out) {
    int i = blockIdx.x * 256 + threadIdx.x;
    if (i < NP * 64) {
        int c = i & 63;
        out[i] = fmaxf(g_ss[Z_OFF + c] * g_z[i] + g_ss[Z_OFF + 64 + c], 0.f);
    }
}

// ---------------- launch ----------------
extern "C" void kernel_launch(void* const* d_in, const int* in_sizes, int n_in,
                              void* d_out, int out_size) {
    const float* xyz   = (const float*)d_in[0];
    const float* cov   = (const float*)d_in[1];
    const float* feats = (const float*)d_in[2];
    const int*   knn   = (const int*)  d_in[3];
    const float* fw1 = (const float*)d_in[4];
    const float* fb1 = (const float*)d_in[5];
    const float* fg1 = (const float*)d_in[6];
    const float* fbe1 = (const float*)d_in[7];
    const float* fw2 = (const float*)d_in[8];
    const float* fb2 = (const float*)d_in[9];
    const float* fg2 = (const float*)d_in[10];
    const float* fbe2 = (const float*)d_in[11];
    const float* ww1 = (const float*)d_in[12];
    const float* wb1 = (const float*)d_in[13];
    const float* wg1 = (const float*)d_in[14];
    const float* wbe1 = (const float*)d_in[15];
    const float* ww2 = (const float*)d_in[16];
    const float* wb2 = (const float*)d_in[17];
    const float* wg2 = (const float*)d_in[18];
    const float* wbe2 = (const float*)d_in[19];
    const float* ww3 = (const float*)d_in[20];
    const float* wb3 = (const float*)d_in[21];
    const float* wg3 = (const float*)d_in[22];
    const float* wbe3 = (const float*)d_in[23];
    const float* lin_w = (const float*)d_in[24];
    const float* lin_b = (const float*)d_in[25];
    const float* bng = (const float*)d_in[26];
    const float* bnb = (const float*)d_in[27];
    float* out = (float*)d_out;

    const float invNK = 1.f / (float)NK;
    const float invN  = 1.f / (float)NP;

    k_zero<<<(NP + 255) / 256, 256>>>();
    k_cnt<<<(NK + 255) / 256, 256>>>(knn);

    // stage 1
    k_fconv<0><<<1024, 256>>>(feats, fw1, fb1);
    k_w1<<<2048, 256>>>(xyz, cov, feats, knn, ww1, wb1);
    k_fin<<<1, 64>>>(F1_OFF, fg1, fbe1, 64, invNK);
    k_fin<<<1, 64>>>(W1_OFF, wg1, wbe1, 8, invNK);

    // stage 2
    k_fconv<1><<<1024, 256>>>(nullptr, fw2, fb2);
    k_w2<<<2048, 256>>>(ww2, wb2);
    k_fin<<<1, 64>>>(F2_OFF, fg2, fbe2, 64, invNK);
    k_fin<<<1, 64>>>(W2_OFF, wg2, wbe2, 8, invNK);

    // stage 3 (w path only)
    k_w3s<<<2048, 256>>>(ww3, wb3);
    k_fin<<<1, 64>>>(W3_OFF, wg3, wbe3, 16, invNK);

    // einsum + linear + final BN
    k_new<<<NP, 128>>>(knn, ww3, wb3);
    k_lin<<<(NP + 127) / 128, 256>>>(lin_w, lin_b);
    k_fin<<<1, 64>>>(Z_OFF, bng, bnb, 64, invN);
    k_out<<<(NP * 64 + 255) / 256, 256>>>(out);
}